// round 16
// baseline (speedup 1.0000x reference)
#include <cuda_runtime.h>
#include <cuda_bf16.h>
#include <cstdint>

// ---------------- problem constants ----------------
#define BB 2
#define SS 2048
#define DD 2048
#define HH 16
#define NOPE 128
#define ROPE 64
#define VDIM 128
#define QKD 192           // NOPE + ROPE
#define KV_RANK 512
#define KV_A (KV_RANK + ROPE)   // 576
#define KV_PROJ (HH * (NOPE + VDIM)) // 4096
#define QKV_N (HH * QKD + KV_A)      // 3648 (merged q + kv_a projection)
#define EPSV 1e-6f
#define ATT_SCALE 0.07216878364870323f  // 192^-0.5

// ---------------- fp32 scratch ----------------
__device__ __align__(16) float g_qkv   [(size_t)BB * SS * QKV_N];   // [B,S,3648]

// ---------------- bf16 hi/lo scratch ----------------
__device__ __align__(16) __nv_bfloat16 g_xh    [(size_t)BB * SS * DD];
__device__ __align__(16) __nv_bfloat16 g_xl    [(size_t)BB * SS * DD];
__device__ __align__(16) __nv_bfloat16 g_wqkvh [(size_t)QKV_N * DD];
__device__ __align__(16) __nv_bfloat16 g_wqkvl [(size_t)QKV_N * DD];
__device__ __align__(16) __nv_bfloat16 g_wkvbh [(size_t)KV_PROJ * KV_RANK];
__device__ __align__(16) __nv_bfloat16 g_wkvbl [(size_t)KV_PROJ * KV_RANK];
__device__ __align__(16) __nv_bfloat16 g_woh   [(size_t)DD * DD];
__device__ __align__(16) __nv_bfloat16 g_wol   [(size_t)DD * DD];
__device__ __align__(16) __nv_bfloat16 g_kvnh  [(size_t)BB * SS * KV_RANK];
__device__ __align__(16) __nv_bfloat16 g_kvnl  [(size_t)BB * SS * KV_RANK];
__device__ __align__(16) __nv_bfloat16 g_Qh    [(size_t)BB * HH * SS * QKD];
__device__ __align__(16) __nv_bfloat16 g_Ql    [(size_t)BB * HH * SS * QKD];
__device__ __align__(16) __nv_bfloat16 g_Kh    [(size_t)BB * HH * SS * QKD];
__device__ __align__(16) __nv_bfloat16 g_Kl    [(size_t)BB * HH * SS * QKD];
__device__ __align__(16) __nv_bfloat16 g_Vth   [(size_t)BB * HH * VDIM * SS];
__device__ __align__(16) __nv_bfloat16 g_Vtl   [(size_t)BB * HH * VDIM * SS];
__device__ __align__(16) __nv_bfloat16 g_a2h   [(size_t)BB * SS * HH * VDIM];
__device__ __align__(16) __nv_bfloat16 g_a2l   [(size_t)BB * SS * HH * VDIM];

// ---------------- helpers ----------------
__device__ __forceinline__ uint32_t smem_u32(const void* p) {
    uint32_t a;
    asm("{ .reg .u64 t; cvta.to.shared.u64 t, %1; cvt.u32.u64 %0, t; }" : "=r"(a) : "l"(p));
    return a;
}
__device__ __forceinline__ void split2(float x, __nv_bfloat16& h, __nv_bfloat16& l) {
    h = __float2bfloat16_rn(x);
    l = __float2bfloat16_rn(x - __bfloat162float(h));
}
__device__ __forceinline__ void packP(float a, float b, unsigned& hi, unsigned& lo) {
    __nv_bfloat16 ha = __float2bfloat16_rn(a);
    __nv_bfloat16 hb = __float2bfloat16_rn(b);
    __nv_bfloat16 la = __float2bfloat16_rn(a - __bfloat162float(ha));
    __nv_bfloat16 lb = __float2bfloat16_rn(b - __bfloat162float(hb));
    hi = ((unsigned)__bfloat16_as_ushort(hb) << 16) | __bfloat16_as_ushort(ha);
    lo = ((unsigned)__bfloat16_as_ushort(lb) << 16) | __bfloat16_as_ushort(la);
}
__device__ __forceinline__ void cp16(uint32_t d, const void* s) {
    asm volatile("cp.async.cg.shared.global [%0], [%1], 16;" :: "r"(d), "l"(s));
}
__device__ __forceinline__ void cp16z(uint32_t d, const void* s, unsigned bytes) {
    asm volatile("cp.async.cg.shared.global [%0], [%1], 16, %2;" :: "r"(d), "l"(s), "r"(bytes));
}

#define MMA16816(d, a, b) \
    asm volatile("mma.sync.aligned.m16n8k16.row.col.f32.bf16.bf16.f32 " \
                 "{%0,%1,%2,%3}, {%4,%5,%6,%7}, {%8,%9}, {%0,%1,%2,%3};" \
                 : "+f"((d)[0]), "+f"((d)[1]), "+f"((d)[2]), "+f"((d)[3]) \
                 : "r"((a)[0]), "r"((a)[1]), "r"((a)[2]), "r"((a)[3]), \
                   "r"((b)[0]), "r"((b)[1]))

#define LDMX4(r, ad) \
    asm volatile("ldmatrix.sync.aligned.m8n8.x4.shared.b16 {%0,%1,%2,%3}, [%4];" \
                 : "=r"((r)[0]), "=r"((r)[1]), "=r"((r)[2]), "=r"((r)[3]) : "r"(ad))
#define LDMX2(r, ad) \
    asm volatile("ldmatrix.sync.aligned.m8n8.x2.shared.b16 {%0,%1}, [%2];" \
                 : "=r"((r)[0]), "=r"((r)[1]) : "r"(ad))

// ======== bf16x3 GEMM: CTA 128x128, warp 64x32, 3-stage cp.async ==============
#define MOFF 8192u
#define STG  32768u
#define GEMM3_SMEM 98304

__device__ __forceinline__ void g3_issue(
    uint32_t sb,
    const __nv_bfloat16* __restrict__ Ah, const __nv_bfloat16* __restrict__ Al,
    const __nv_bfloat16* __restrict__ Bh, const __nv_bfloat16* __restrict__ Bl,
    int bm, int bn, int N, int lda, int ldb, int k0, int tid)
{
#pragma unroll
    for (int half = 0; half < 2; half++) {
        int r  = (tid >> 2) + half * 64;
        int sg = tid & 3;
        int p  = sg ^ ((r >> 1) & 3);
        uint32_t d = sb + (uint32_t)(r * 64 + p * 16);
        long long ko = (long long)k0 + sg * 8;
        cp16(d,        Ah + (long long)(bm + r) * lda + ko);
        cp16(d + MOFF, Al + (long long)(bm + r) * lda + ko);
        int gn = bn + r;
        unsigned bytes = (gn < N) ? 16u : 0u;
        int gr = (gn < N) ? gn : 0;
        cp16z(d + 2 * MOFF, Bh + (long long)gr * ldb + ko, bytes);
        cp16z(d + 3 * MOFF, Bl + (long long)gr * ldb + ko, bytes);
    }
    asm volatile("cp.async.commit_group;" ::: "memory");
}

// shared mainloop body (macro to reuse in both kernels)
#define G3_MAINLOOP(K_, lda_, ldb_, N_) \
    const int nc = (K_) >> 5; \
    g3_issue(smb,       Ah, Al, Bh, Bl, bm, bn, (N_), (lda_), (ldb_), 0,  tid); \
    g3_issue(smb + STG, Ah, Al, Bh, Bl, bm, bn, (N_), (lda_), (ldb_), 32, tid); \
    const int l15 = lane & 15; \
    const int l7  = lane & 7; \
    const uint32_t aSel = (uint32_t)(lane >> 4); \
    const uint32_t bSel = (uint32_t)(l15 >> 3); \
    const uint32_t swzA = (uint32_t)((l15 >> 1) & 3); \
    const uint32_t swzB = (uint32_t)((l7 >> 1) & 3); \
    const uint32_t aBase = smb + (uint32_t)((wm * 64 + l15) * 64); \
    const uint32_t bBase = smb + 2u * MOFF + (uint32_t)((wn * 32 + l7) * 64); \
    for (int c = 0; c < nc; c++) { \
        asm volatile("cp.async.wait_group 1;" ::: "memory"); \
        __syncthreads(); \
        if (c + 2 < nc) { \
            g3_issue(smb + (uint32_t)((c + 2) % 3) * STG, \
                     Ah, Al, Bh, Bl, bm, bn, (N_), (lda_), (ldb_), (c + 2) << 5, tid); \
        } else { \
            asm volatile("cp.async.commit_group;" ::: "memory"); \
        } \
        const uint32_t so = (uint32_t)(c % 3) * STG; \
        _Pragma("unroll") \
        for (int kk = 0; kk < 2; kk++) { \
            const uint32_t cA = (uint32_t)(kk * 2) + aSel; \
            const uint32_t cB = (uint32_t)(kk * 2) + bSel; \
            unsigned bhf[4][2], blf[4][2]; \
            _Pragma("unroll") \
            for (int nf = 0; nf < 4; nf++) { \
                uint32_t ad = bBase + so + (uint32_t)(nf * 512) + ((cB ^ swzB) << 4); \
                LDMX2(bhf[nf], ad); \
                LDMX2(blf[nf], ad + MOFF); \
            } \
            _Pragma("unroll") \
            for (int mf = 0; mf < 4; mf++) { \
                uint32_t ad = aBase + so + (uint32_t)(mf * 1024) + ((cA ^ swzA) << 4); \
                unsigned ahf[4], alf[4]; \
                LDMX4(ahf, ad); \
                LDMX4(alf, ad + MOFF); \
                _Pragma("unroll") \
                for (int nf = 0; nf < 4; nf++) { \
                    MMA16816(acc[mf][nf], ahf, bhf[nf]); \
                    MMA16816(acc[mf][nf], ahf, blf[nf]); \
                    MMA16816(acc[mf][nf], alf, bhf[nf]); \
                } \
            } \
        } \
    }

__global__ __launch_bounds__(256, 2) void gemm3(
    const __nv_bfloat16* __restrict__ Ah, const __nv_bfloat16* __restrict__ Al,
    const __nv_bfloat16* __restrict__ Bh, const __nv_bfloat16* __restrict__ Bl,
    float* __restrict__ C,
    int M, int N, int K, int lda, int ldb, int ldc)
{
    extern __shared__ char sm[];
    const int tid  = threadIdx.x;
    const int lane = tid & 31;
    const int wid  = tid >> 5;
    const int g    = lane >> 2;
    const int tig  = lane & 3;
    const int wm   = wid >> 2;
    const int wn   = wid & 3;
    const int bm = blockIdx.y * 128;
    const int bn = blockIdx.x * 128;
    const uint32_t smb = smem_u32(sm);

    float acc[4][4][4];
#pragma unroll
    for (int i = 0; i < 4; i++)
#pragma unroll
        for (int j = 0; j < 4; j++)
#pragma unroll
            for (int q = 0; q < 4; q++) acc[i][j][q] = 0.f;

    G3_MAINLOOP(K, lda, ldb, N)

#pragma unroll
    for (int mf = 0; mf < 4; mf++) {
#pragma unroll
        for (int nf = 0; nf < 4; nf++) {
            int row = bm + wm * 64 + mf * 16 + g;
            int col = bn + wn * 32 + nf * 8 + 2 * tig;
            if (col < N) {
                float* p0 = C + (long long)row * ldc + col;
                p0[0] = acc[mf][nf][0];
                p0[1] = acc[mf][nf][1];
                float* p1 = p0 + (long long)8 * ldc;
                p1[0] = acc[mf][nf][2];
                p1[1] = acc[mf][nf][3];
            }
        }
    }
}

// ==== kv_proj GEMM with fused epilogue: K-nope -> Kh/Kl, V -> Vt (transposed) =
// A = kvn [4096,512] bf16x2, B = wkvb [4096,512] bf16x2.
// n-tile 2t   = head t, k_nope d 0..127  -> Kh/Kl [bh][s][0..128)
// n-tile 2t+1 = head t, v d 0..127       -> Vth/Vtl [bh][d][s] via smem transpose
__global__ __launch_bounds__(256, 2) void gemm_kv(
    const __nv_bfloat16* __restrict__ Ah, const __nv_bfloat16* __restrict__ Al,
    const __nv_bfloat16* __restrict__ Bh, const __nv_bfloat16* __restrict__ Bl,
    __nv_bfloat16* __restrict__ Kh, __nv_bfloat16* __restrict__ Kl,
    __nv_bfloat16* __restrict__ Vth, __nv_bfloat16* __restrict__ Vtl)
{
    extern __shared__ char sm[];
    const int tid  = threadIdx.x;
    const int lane = tid & 31;
    const int wid  = tid >> 5;
    const int g    = lane >> 2;
    const int tig  = lane & 3;
    const int wm   = wid >> 2;
    const int wn   = wid & 3;
    const int bm = blockIdx.y * 128;
    const int bn = blockIdx.x * 128;
    const int h   = blockIdx.x >> 1;
    const int isV = blockIdx.x & 1;
    const uint32_t smb = smem_u32(sm);

    float acc[4][4][4];
#pragma unroll
    for (int i = 0; i < 4; i++)
#pragma unroll
        for (int j = 0; j < 4; j++)
#pragma unroll
            for (int q = 0; q < 4; q++) acc[i][j][q] = 0.f;

    G3_MAINLOOP(KV_RANK, KV_RANK, KV_RANK, KV_PROJ)

    const int b = bm >> 11;               // token block -> batch
    const int sbase = bm & 2047;

    if (!isV) {
        // K-nope: write [bh][s][d], d = local col
#pragma unroll
        for (int mf = 0; mf < 4; mf++) {
#pragma unroll
            for (int nf = 0; nf < 4; nf++) {
                int s = sbase + wm * 64 + mf * 16 + g;
                int d = wn * 32 + nf * 8 + 2 * tig;
                long long o0 = ((long long)(b * HH + h) * SS + s) * QKD + d;
                long long o1 = o0 + 8ll * QKD;
                unsigned hh, ll;
                packP(acc[mf][nf][0], acc[mf][nf][1], hh, ll);
                *(unsigned*)(Kh + o0) = hh;
                *(unsigned*)(Kl + o0) = ll;
                packP(acc[mf][nf][2], acc[mf][nf][3], hh, ll);
                *(unsigned*)(Kh + o1) = hh;
                *(unsigned*)(Kl + o1) = ll;
            }
        }
    } else {
        // V: transpose through smem, write [bh][d][s] coalesced along s
        __syncthreads();
        float* vs = (float*)sm;           // [128 d][132] pitch
#pragma unroll
        for (int mf = 0; mf < 4; mf++) {
#pragma unroll
            for (int nf = 0; nf < 4; nf++) {
                int rl = wm * 64 + mf * 16 + g;
                int cl = wn * 32 + nf * 8 + 2 * tig;
                vs[cl * 132 + rl]           = acc[mf][nf][0];
                vs[(cl + 1) * 132 + rl]     = acc[mf][nf][1];
                vs[cl * 132 + rl + 8]       = acc[mf][nf][2];
                vs[(cl + 1) * 132 + rl + 8] = acc[mf][nf][3];
            }
        }
        __syncthreads();
        const int d  = tid >> 1;
        const int sh = tid & 1;
        const long long o = ((long long)((b * HH + h) * VDIM + d)) * SS
                          + sbase + sh * 64;
        const float* src = vs + d * 132 + sh * 64;
#pragma unroll
        for (int i = 0; i < 64; i += 2) {
            unsigned hh, ll;
            packP(src[i], src[i + 1], hh, ll);
            *(unsigned*)(Vth + o + i) = hh;
            *(unsigned*)(Vtl + o + i) = ll;
        }
    }
}

// ================= fused flash attention (bf16x3, online softmax) =============
#define FA_KOFF 98304u
#define FA_QLO  49152u
#define FA_VOFF 147456u
#define FA_SMEM 212992

__device__ __forceinline__ void fa_issueK(
    uint32_t smb, int stage,
    const __nv_bfloat16* __restrict__ Khp, const __nv_bfloat16* __restrict__ Klp,
    int c, int tid)
{
#pragma unroll
    for (int it = 0; it < 2; it++) {
        int u = tid + (it << 8);
        int r = u >> 2, sg = u & 3;
        int p = sg ^ ((r >> 1) & 3);
        uint32_t d = smb + FA_KOFF + (uint32_t)(stage * 16384 + r * 64 + p * 16);
        long long off = (long long)r * QKD + c * 32 + sg * 8;
        cp16(d,         Khp + off);
        cp16(d + 8192u, Klp + off);
    }
    asm volatile("cp.async.commit_group;" ::: "memory");
}

__device__ __forceinline__ void fa_issueV(
    uint32_t smb,
    const __nv_bfloat16* __restrict__ Vhp, const __nv_bfloat16* __restrict__ Vlp,
    int j, int tid)
{
#pragma unroll
    for (int it = 0; it < 8; it++) {
        int u = tid + (it << 8);
        int cb = u >> 9, v = u & 511;
        int r = v >> 2, sg = v & 3;
        int p = sg ^ ((r >> 1) & 3);
        uint32_t d = smb + FA_VOFF + (uint32_t)(cb * 16384 + r * 64 + p * 16);
        long long off = (long long)r * SS + j * 128 + cb * 32 + sg * 8;
        cp16(d,         Vhp + off);
        cp16(d + 8192u, Vlp + off);
    }
    asm volatile("cp.async.commit_group;" ::: "memory");
}

__global__ __launch_bounds__(256, 1) void fa_kernel(
    const __nv_bfloat16* __restrict__ Qh, const __nv_bfloat16* __restrict__ Ql,
    const __nv_bfloat16* __restrict__ Kh, const __nv_bfloat16* __restrict__ Kl,
    const __nv_bfloat16* __restrict__ Vth, const __nv_bfloat16* __restrict__ Vtl,
    __nv_bfloat16* __restrict__ a2h, __nv_bfloat16* __restrict__ a2l)
{
    extern __shared__ char sm[];
    const int tid  = threadIdx.x;
    const int lane = tid & 31;
    const int wid  = tid >> 5;
    const int g    = lane >> 2;
    const int tig  = lane & 3;
    const int qt   = blockIdx.x;
    const int bh   = blockIdx.y;
    const int b    = bh >> 4, h = bh & 15;
    const uint32_t smb = smem_u32(sm);

    const long long qkBase = (long long)bh * SS * QKD;
    const __nv_bfloat16* QhB = Qh + qkBase + (long long)qt * 128 * QKD;
    const __nv_bfloat16* QlB = Ql + qkBase + (long long)qt * 128 * QKD;
    const __nv_bfloat16* KhB = Kh + qkBase;
    const __nv_bfloat16* KlB = Kl + qkBase;
    const __nv_bfloat16* VhB = Vth + (long long)bh * VDIM * SS;
    const __nv_bfloat16* VlB = Vtl + (long long)bh * VDIM * SS;

    {
#pragma unroll
        for (int c = 0; c < 6; c++) {
#pragma unroll
            for (int it = 0; it < 2; it++) {
                int u = tid + (it << 8);
                int r = u >> 2, sg = u & 3;
                int p = sg ^ ((r >> 1) & 3);
                uint32_t d = smb + (uint32_t)(c * 8192 + r * 64 + p * 16);
                long long off = (long long)r * QKD + c * 32 + sg * 8;
                cp16(d,          QhB + off);
                cp16(d + FA_QLO, QlB + off);
            }
        }
        asm volatile("cp.async.commit_group;" ::: "memory");
    }
    fa_issueK(smb, 0, KhB, KlB, 0, tid);
    fa_issueK(smb, 1, KhB, KlB, 1, tid);

    float sacc[16][4], oacc[16][4];
    float m0 = -1e30f, m1 = -1e30f, l0 = 0.f, l1 = 0.f;
#pragma unroll
    for (int nf = 0; nf < 16; nf++)
#pragma unroll
        for (int q = 0; q < 4; q++) oacc[nf][q] = 0.f;

    const int l15 = lane & 15;
    const int l7  = lane & 7;
    const uint32_t aSel = (uint32_t)(lane >> 4);
    const uint32_t bSel = (uint32_t)(l15 >> 3);
    const uint32_t swzA = (uint32_t)((l15 >> 1) & 3);
    const uint32_t swzB = (uint32_t)((l7 >> 1) & 3);
    const uint32_t aRow = smb + (uint32_t)((wid * 16 + l15) * 64);
    const uint32_t kRow = smb + FA_KOFF + (uint32_t)(l7 * 64);
    const uint32_t vRow = smb + FA_VOFF + (uint32_t)(l7 * 64);

    for (int j = 0; j < 16; j++) {
        __syncthreads();
        fa_issueV(smb, VhB, VlB, j, tid);

#pragma unroll
        for (int nf = 0; nf < 16; nf++) {
            sacc[nf][0] = 0.f; sacc[nf][1] = 0.f; sacc[nf][2] = 0.f; sacc[nf][3] = 0.f;
        }

        for (int c = 0; c < 6; c++) {
            const int gc = j * 6 + c;
            if (c < 2) asm volatile("cp.async.wait_group 2;" ::: "memory");
            else       asm volatile("cp.async.wait_group 1;" ::: "memory");
            __syncthreads();

            const int gcI = gc + 2;
            if (gcI < 96) {
                const int jI = gcI / 6, cI = gcI % 6;
                fa_issueK(smb, gcI % 3,
                          KhB + (long long)jI * 128 * QKD,
                          KlB + (long long)jI * 128 * QKD, cI, tid);
            } else {
                asm volatile("cp.async.commit_group;" ::: "memory");
            }

            const uint32_t aB = aRow + (uint32_t)(c * 8192);
            const uint32_t kB = kRow + (uint32_t)((gc % 3) * 16384);
#pragma unroll
            for (int kk = 0; kk < 2; kk++) {
                const uint32_t cA = (uint32_t)(kk * 2) + aSel;
                const uint32_t cB = (uint32_t)(kk * 2) + bSel;
                uint32_t aAd = aB + ((cA ^ swzA) << 4);
                unsigned ah[4], al[4];
                LDMX4(ah, aAd);
                LDMX4(al, aAd + FA_QLO);
#pragma unroll
                for (int nf = 0; nf < 16; nf++) {
                    uint32_t bAd = kB + (uint32_t)(nf * 512) + ((cB ^ swzB) << 4);
                    unsigned kh2[2], kl2[2];
                    LDMX2(kh2, bAd);
                    LDMX2(kl2, bAd + 8192u);
                    MMA16816(sacc[nf], ah, kh2);
                    MMA16816(sacc[nf], ah, kl2);
                    MMA16816(sacc[nf], al, kh2);
                }
            }
        }

        float mx0 = -1e30f, mx1 = -1e30f;
#pragma unroll
        for (int nf = 0; nf < 16; nf++) {
            mx0 = fmaxf(mx0, fmaxf(sacc[nf][0], sacc[nf][1]));
            mx1 = fmaxf(mx1, fmaxf(sacc[nf][2], sacc[nf][3]));
        }
        mx0 = fmaxf(mx0, __shfl_xor_sync(0xffffffffu, mx0, 1));
        mx0 = fmaxf(mx0, __shfl_xor_sync(0xffffffffu, mx0, 2));
        mx1 = fmaxf(mx1, __shfl_xor_sync(0xffffffffu, mx1, 1));
        mx1 = fmaxf(mx1, __shfl_xor_sync(0xffffffffu, mx1, 2));
        const float mn0 = fmaxf(m0, mx0 * ATT_SCALE);
        const float mn1 = fmaxf(m1, mx1 * ATT_SCALE);
        const float cf0 = __expf(m0 - mn0);
        const float cf1 = __expf(m1 - mn1);
        float s0 = 0.f, s1 = 0.f;
#pragma unroll
        for (int nf = 0; nf < 16; nf++) {
            float p0 = __expf(sacc[nf][0] * ATT_SCALE - mn0);
            float p1 = __expf(sacc[nf][1] * ATT_SCALE - mn0);
            float p2 = __expf(sacc[nf][2] * ATT_SCALE - mn1);
            float p3 = __expf(sacc[nf][3] * ATT_SCALE - mn1);
            sacc[nf][0] = p0; sacc[nf][1] = p1; sacc[nf][2] = p2; sacc[nf][3] = p3;
            s0 += p0 + p1; s1 += p2 + p3;
        }
        s0 += __shfl_xor_sync(0xffffffffu, s0, 1);
        s0 += __shfl_xor_sync(0xffffffffu, s0, 2);
        s1 += __shfl_xor_sync(0xffffffffu, s1, 1);
        s1 += __shfl_xor_sync(0xffffffffu, s1, 2);
        l0 = l0 * cf0 + s0; l1 = l1 * cf1 + s1;
        m0 = mn0; m1 = mn1;
#pragma unroll
        for (int nf = 0; nf < 16; nf++) {
            oacc[nf][0] *= cf0; oacc[nf][1] *= cf0;
            oacc[nf][2] *= cf1; oacc[nf][3] *= cf1;
        }

#pragma unroll
        for (int kc = 0; kc < 8; kc++) {
            unsigned ah[4], al[4];
            packP(sacc[2 * kc][0],     sacc[2 * kc][1],     ah[0], al[0]);
            packP(sacc[2 * kc][2],     sacc[2 * kc][3],     ah[1], al[1]);
            packP(sacc[2 * kc + 1][0], sacc[2 * kc + 1][1], ah[2], al[2]);
            packP(sacc[2 * kc + 1][2], sacc[2 * kc + 1][3], ah[3], al[3]);
            const uint32_t vB = vRow + (uint32_t)((kc >> 1) * 16384);
            const uint32_t cV = (uint32_t)((kc & 1) * 2) + bSel;
#pragma unroll
            for (int nf = 0; nf < 16; nf++) {
                uint32_t bAd = vB + (uint32_t)(nf * 512) + ((cV ^ swzB) << 4);
                unsigned vh2[2], vl2[2];
                LDMX2(vh2, bAd);
                LDMX2(vl2, bAd + 8192u);
                MMA16816(oacc[nf], ah, vh2);
                MMA16816(oacc[nf], ah, vl2);
                MMA16816(oacc[nf], al, vh2);
            }
        }
    }

    const float li0 = 1.f / l0, li1 = 1.f / l1;
    const int srow = qt * 128 + wid * 16 + g;
    const long long base0 = ((long long)(b * SS) + srow) * (HH * VDIM) + h * VDIM;
    const long long base1 = base0 + 8ll * (HH * VDIM);
#pragma unroll
    for (int nf = 0; nf < 16; nf++) {
        const int d = nf * 8 + 2 * tig;
        unsigned hh, ll;
        packP(oacc[nf][0] * li0, oacc[nf][1] * li0, hh, ll);
        *(unsigned*)(a2h + base0 + d) = hh;
        *(unsigned*)(a2l + base0 + d) = ll;
        packP(oacc[nf][2] * li1, oacc[nf][3] * li1, hh, ll);
        *(unsigned*)(a2h + base1 + d) = hh;
        *(unsigned*)(a2l + base1 + d) = ll;
    }
}

// ---------------- fp32 -> bf16 hi/lo converter ----------------
__global__ void convert_kernel(const float* __restrict__ in,
                               __nv_bfloat16* __restrict__ hp,
                               __nv_bfloat16* __restrict__ lp, long long n4)
{
    for (long long i = (long long)blockIdx.x * 256 + threadIdx.x; i < n4;
         i += (long long)gridDim.x * 256) {
        float4 v = ((const float4*)in)[i];
        __nv_bfloat16 h0, h1, h2, h3, l0, l1, l2, l3;
        split2(v.x, h0, l0); split2(v.y, h1, l1);
        split2(v.z, h2, l2); split2(v.w, h3, l3);
        uint2 hh, ll;
        hh.x = ((unsigned)__bfloat16_as_ushort(h1) << 16) | __bfloat16_as_ushort(h0);
        hh.y = ((unsigned)__bfloat16_as_ushort(h3) << 16) | __bfloat16_as_ushort(h2);
        ll.x = ((unsigned)__bfloat16_as_ushort(l1) << 16) | __bfloat16_as_ushort(l0);
        ll.y = ((unsigned)__bfloat16_as_ushort(l3) << 16) | __bfloat16_as_ushort(l2);
        ((uint2*)hp)[i] = hh;
        ((uint2*)lp)[i] = ll;
    }
}

// ---------------- rmsnorm over KV_RANK (reads merged qkv buffer) --------------
__global__ void rmsnorm_kernel(const float* __restrict__ qkv,
                               const float* __restrict__ w,
                               __nv_bfloat16* __restrict__ oh,
                               __nv_bfloat16* __restrict__ ol)
{
    const int row = blockIdx.x;
    const float* x = qkv + (long long)row * QKV_N + HH * QKD;
    __shared__ float red[256];
    float ss = 0.f;
    for (int i = threadIdx.x; i < KV_RANK; i += 256) { float v = x[i]; ss += v * v; }
    red[threadIdx.x] = ss; __syncthreads();
    for (int st = 128; st > 0; st >>= 1) {
        if (threadIdx.x < st) red[threadIdx.x] += red[threadIdx.x + st];
        __syncthreads();
    }
    float scale = rsqrtf(red[0] / (float)KV_RANK + EPSV);
    for (int i = threadIdx.x; i < KV_RANK; i += 256) {
        float v = x[i] * scale * w[i];
        __nv_bfloat16 h, l; split2(v, h, l);
        oh[(long long)row * KV_RANK + i] = h;
        ol[(long long)row * KV_RANK + i] = l;
    }
}

// ---------------- RoPE prep: Q (full) + K rope-part only ----------------------
__global__ void prepare_kernel(const float* __restrict__ qkv,
                               const float* __restrict__ cosb,
                               const float* __restrict__ sinb,
                               __nv_bfloat16* __restrict__ Qh, __nv_bfloat16* __restrict__ Ql,
                               __nv_bfloat16* __restrict__ Kh, __nv_bfloat16* __restrict__ Kl)
{
    const int bs = blockIdx.x;
    const int b = bs / SS, s = bs % SS;
    const float* cs = cosb + (long long)s * ROPE;
    const float* sn = sinb + (long long)s * ROPE;

    __shared__ float kpe[ROPE];
    if (threadIdx.x < ROPE) {
        int j = threadIdx.x;
        const float* kp = qkv + (long long)bs * QKV_N + HH * QKD + KV_RANK;
        float x  = kp[j];
        float xr = (j < 32) ? -kp[j + 32] : kp[j - 32];
        kpe[j] = x * cs[j] + xr * sn[j];
    }
    __syncthreads();

    const float* qrow = qkv + (long long)bs * QKV_N;

    for (int idx = threadIdx.x; idx < HH * QKD; idx += blockDim.x) {
        int h = idx / QKD, d = idx % QKD;
        long long off = (((long long)(b * HH + h)) * SS + s) * QKD + d;
        float qv;
        if (d < NOPE) {
            qv = qrow[h * QKD + d];
        } else {
            int j = d - NOPE;
            float x  = qrow[h * QKD + NOPE + j];
            float xr = (j < 32) ? -qrow[h * QKD + NOPE + j + 32]
                                :  qrow[h * QKD + NOPE + j - 32];
            qv = x * cs[j] + xr * sn[j];
        }
        __nv_bfloat16 hh, ll;
        split2(qv, hh, ll); Qh[off] = hh; Ql[off] = ll;
    }
    // K rope part (d 128..191), broadcast across heads
    for (int idx = threadIdx.x; idx < HH * ROPE; idx += blockDim.x) {
        int h = idx >> 6, j = idx & 63;
        long long off = (((long long)(b * HH + h)) * SS + s) * QKD + NOPE + j;
        __nv_bfloat16 hh, ll; split2(kpe[j], hh, ll);
        Kh[off] = hh; Kl[off] = ll;
    }
}

// ---------------- launch ----------------
extern "C" void kernel_launch(void* const* d_in, const int* in_sizes, int n_in,
                              void* d_out, int out_size)
{
    const float* x    = (const float*)d_in[0];
    const float* cosb = (const float*)d_in[1];
    const float* sinb = (const float*)d_in[2];
    const float* wq   = (const float*)d_in[3];
    const float* wkva = (const float*)d_in[4];
    const float* kvw  = (const float*)d_in[5];
    const float* wkvb = (const float*)d_in[6];
    const float* wo   = (const float*)d_in[7];
    float* out = (float*)d_out;

    cudaFuncSetAttribute(gemm3,   cudaFuncAttributeMaxDynamicSharedMemorySize, GEMM3_SMEM);
    cudaFuncSetAttribute(gemm_kv, cudaFuncAttributeMaxDynamicSharedMemorySize, GEMM3_SMEM);
    cudaFuncSetAttribute(fa_kernel, cudaFuncAttributeMaxDynamicSharedMemorySize, FA_SMEM);

    float *qkv;
    cudaGetSymbolAddress((void**)&qkv, g_qkv);

    __nv_bfloat16 *xh, *xl, *wqkvh, *wqkvl, *wkvbh, *wkvbl, *woh, *wol;
    __nv_bfloat16 *kvnh, *kvnl, *Qh, *Ql, *Kh, *Kl, *Vth, *Vtl, *a2h, *a2l;
    cudaGetSymbolAddress((void**)&xh,    g_xh);    cudaGetSymbolAddress((void**)&xl,    g_xl);
    cudaGetSymbolAddress((void**)&wqkvh, g_wqkvh); cudaGetSymbolAddress((void**)&wqkvl, g_wqkvl);
    cudaGetSymbolAddress((void**)&wkvbh, g_wkvbh); cudaGetSymbolAddress((void**)&wkvbl, g_wkvbl);
    cudaGetSymbolAddress((void**)&woh,   g_woh);   cudaGetSymbolAddress((void**)&wol,   g_wol);
    cudaGetSymbolAddress((void**)&kvnh,  g_kvnh);  cudaGetSymbolAddress((void**)&kvnl,  g_kvnl);
    cudaGetSymbolAddress((void**)&Qh,    g_Qh);    cudaGetSymbolAddress((void**)&Ql,    g_Ql);
    cudaGetSymbolAddress((void**)&Kh,    g_Kh);    cudaGetSymbolAddress((void**)&Kl,    g_Kl);
    cudaGetSymbolAddress((void**)&Vth,   g_Vth);   cudaGetSymbolAddress((void**)&Vtl,   g_Vtl);
    cudaGetSymbolAddress((void**)&a2h,   g_a2h);   cudaGetSymbolAddress((void**)&a2l,   g_a2l);

    const int M = BB * SS;   // 4096

    // 0) pre-split inputs/weights to bf16 hi/lo (wq+wkv_a share one buffer)
    convert_kernel<<<1024, 256>>>(x,    xh,    xl,    (long long)BB * SS * DD / 4);
    convert_kernel<<<1024, 256>>>(wq,   wqkvh, wqkvl, (long long)(HH * QKD) * DD / 4);
    convert_kernel<<<1024, 256>>>(wkva, wqkvh + (size_t)(HH * QKD) * DD,
                                        wqkvl + (size_t)(HH * QKD) * DD,
                                        (long long)KV_A * DD / 4);
    convert_kernel<<<1024, 256>>>(wkvb, wkvbh, wkvbl, (long long)KV_PROJ * KV_RANK / 4);
    convert_kernel<<<1024, 256>>>(wo,   woh,   wol,   (long long)DD * DD / 4);

    // 1) qkv_raw = X @ [wq; wkv_a]^T   [4096,3648] K=2048
    gemm3<<<dim3((QKV_N + 127) / 128, M / 128, 1), 256, GEMM3_SMEM>>>(
        xh, xl, wqkvh, wqkvl, qkv, M, QKV_N, DD, DD, DD, QKV_N);

    // 2) rmsnorm -> bf16 hi/lo
    rmsnorm_kernel<<<M, 256>>>(qkv, kvw, kvnh, kvnl);

    // 3) kv_proj GEMM with fused K/V epilogue (writes Kh/Kl d<128 and Vt)
    gemm_kv<<<dim3(KV_PROJ / 128, M / 128, 1), 256, GEMM3_SMEM>>>(
        kvnh, kvnl, wkvbh, wkvbl, Kh, Kl, Vth, Vtl);

    // 4) RoPE prep: Q full + K rope-part
    prepare_kernel<<<M, 256>>>(qkv, cosb, sinb, Qh, Ql, Kh, Kl);

    // 5) fused attention -> a2h/a2l
    fa_kernel<<<dim3(SS / 128, BB * HH, 1), 256, FA_SMEM>>>(
        Qh, Ql, Kh, Kl, Vth, Vtl, a2h, a2l);

    // 6) out = attn2 @ wo^T      [4096,2048] K=2048
    gemm3<<<dim3(DD / 128, M / 128, 1), 256, GEMM3_SMEM>>>(
        a2h, a2l, woh, wol, out, M, DD, HH * VDIM, HH * VDIM, HH * VDIM, DD);
}

// round 17
// speedup vs baseline: 1.0229x; 1.0229x over previous
#include <cuda_runtime.h>
#include <cuda_bf16.h>
#include <cstdint>

// ---------------- problem constants ----------------
#define BB 2
#define SS 2048
#define DD 2048
#define HH 16
#define NOPE 128
#define ROPE 64
#define VDIM 128
#define QKD 192           // NOPE + ROPE
#define KV_RANK 512
#define KV_A (KV_RANK + ROPE)   // 576
#define KV_PROJ (HH * (NOPE + VDIM)) // 4096
#define QKV_N (HH * QKD + KV_A)      // 3648 (merged q + kv_a projection)
#define EPSV 1e-6f
#define ATT_SCALE 0.07216878364870323f  // 192^-0.5

// ---------------- fp32 scratch ----------------
__device__ __align__(16) float g_qkv   [(size_t)BB * SS * QKV_N];   // [B,S,3648]

// ---------------- bf16 hi/lo scratch ----------------
__device__ __align__(16) __nv_bfloat16 g_xh    [(size_t)BB * SS * DD];
__device__ __align__(16) __nv_bfloat16 g_xl    [(size_t)BB * SS * DD];
__device__ __align__(16) __nv_bfloat16 g_wqkvh [(size_t)QKV_N * DD];
__device__ __align__(16) __nv_bfloat16 g_wqkvl [(size_t)QKV_N * DD];
__device__ __align__(16) __nv_bfloat16 g_wkvbh [(size_t)KV_PROJ * KV_RANK];
__device__ __align__(16) __nv_bfloat16 g_wkvbl [(size_t)KV_PROJ * KV_RANK];
__device__ __align__(16) __nv_bfloat16 g_woh   [(size_t)DD * DD];
__device__ __align__(16) __nv_bfloat16 g_wol   [(size_t)DD * DD];
__device__ __align__(16) __nv_bfloat16 g_kvnh  [(size_t)BB * SS * KV_RANK];
__device__ __align__(16) __nv_bfloat16 g_kvnl  [(size_t)BB * SS * KV_RANK];
__device__ __align__(16) __nv_bfloat16 g_Qh    [(size_t)BB * HH * SS * QKD];
__device__ __align__(16) __nv_bfloat16 g_Ql    [(size_t)BB * HH * SS * QKD];
__device__ __align__(16) __nv_bfloat16 g_Kh    [(size_t)BB * HH * SS * QKD];
__device__ __align__(16) __nv_bfloat16 g_Kl    [(size_t)BB * HH * SS * QKD];
__device__ __align__(16) __nv_bfloat16 g_Vth   [(size_t)BB * HH * VDIM * SS];
__device__ __align__(16) __nv_bfloat16 g_Vtl   [(size_t)BB * HH * VDIM * SS];
__device__ __align__(16) __nv_bfloat16 g_a2h   [(size_t)BB * SS * HH * VDIM];
__device__ __align__(16) __nv_bfloat16 g_a2l   [(size_t)BB * SS * HH * VDIM];

// ---------------- helpers ----------------
__device__ __forceinline__ uint32_t smem_u32(const void* p) {
    uint32_t a;
    asm("{ .reg .u64 t; cvta.to.shared.u64 t, %1; cvt.u32.u64 %0, t; }" : "=r"(a) : "l"(p));
    return a;
}
__device__ __forceinline__ void split2(float x, __nv_bfloat16& h, __nv_bfloat16& l) {
    h = __float2bfloat16_rn(x);
    l = __float2bfloat16_rn(x - __bfloat162float(h));
}
__device__ __forceinline__ void packP(float a, float b, unsigned& hi, unsigned& lo) {
    __nv_bfloat16 ha = __float2bfloat16_rn(a);
    __nv_bfloat16 hb = __float2bfloat16_rn(b);
    __nv_bfloat16 la = __float2bfloat16_rn(a - __bfloat162float(ha));
    __nv_bfloat16 lb = __float2bfloat16_rn(b - __bfloat162float(hb));
    hi = ((unsigned)__bfloat16_as_ushort(hb) << 16) | __bfloat16_as_ushort(ha);
    lo = ((unsigned)__bfloat16_as_ushort(lb) << 16) | __bfloat16_as_ushort(la);
}
__device__ __forceinline__ void cp16(uint32_t d, const void* s) {
    asm volatile("cp.async.cg.shared.global [%0], [%1], 16;" :: "r"(d), "l"(s));
}
__device__ __forceinline__ void cp16z(uint32_t d, const void* s, unsigned bytes) {
    asm volatile("cp.async.cg.shared.global [%0], [%1], 16, %2;" :: "r"(d), "l"(s), "r"(bytes));
}

#define MMA16816(d, a, b) \
    asm volatile("mma.sync.aligned.m16n8k16.row.col.f32.bf16.bf16.f32 " \
                 "{%0,%1,%2,%3}, {%4,%5,%6,%7}, {%8,%9}, {%0,%1,%2,%3};" \
                 : "+f"((d)[0]), "+f"((d)[1]), "+f"((d)[2]), "+f"((d)[3]) \
                 : "r"((a)[0]), "r"((a)[1]), "r"((a)[2]), "r"((a)[3]), \
                   "r"((b)[0]), "r"((b)[1]))

#define LDMX4(r, ad) \
    asm volatile("ldmatrix.sync.aligned.m8n8.x4.shared.b16 {%0,%1,%2,%3}, [%4];" \
                 : "=r"((r)[0]), "=r"((r)[1]), "=r"((r)[2]), "=r"((r)[3]) : "r"(ad))
#define LDMX2(r, ad) \
    asm volatile("ldmatrix.sync.aligned.m8n8.x2.shared.b16 {%0,%1}, [%2];" \
                 : "=r"((r)[0]), "=r"((r)[1]) : "r"(ad))

// ======== bf16x3 GEMM: CTA 128x128, warp 64x32, 3-stage cp.async ==============
#define MOFF 8192u
#define STG  32768u
#define GEMM3_SMEM 98304

__device__ __forceinline__ void g3_issue(
    uint32_t sb,
    const __nv_bfloat16* __restrict__ Ah, const __nv_bfloat16* __restrict__ Al,
    const __nv_bfloat16* __restrict__ Bh, const __nv_bfloat16* __restrict__ Bl,
    int bm, int bn, int N, int lda, int ldb, int k0, int tid)
{
#pragma unroll
    for (int half = 0; half < 2; half++) {
        int r  = (tid >> 2) + half * 64;
        int sg = tid & 3;
        int p  = sg ^ ((r >> 1) & 3);
        uint32_t d = sb + (uint32_t)(r * 64 + p * 16);
        long long ko = (long long)k0 + sg * 8;
        cp16(d,        Ah + (long long)(bm + r) * lda + ko);
        cp16(d + MOFF, Al + (long long)(bm + r) * lda + ko);
        int gn = bn + r;
        unsigned bytes = (gn < N) ? 16u : 0u;
        int gr = (gn < N) ? gn : 0;
        cp16z(d + 2 * MOFF, Bh + (long long)gr * ldb + ko, bytes);
        cp16z(d + 3 * MOFF, Bl + (long long)gr * ldb + ko, bytes);
    }
    asm volatile("cp.async.commit_group;" ::: "memory");
}

// shared mainloop body
#define G3_MAINLOOP(K_, lda_, ldb_, N_) \
    const int nc = (K_) >> 5; \
    g3_issue(smb,       Ah, Al, Bh, Bl, bm, bn, (N_), (lda_), (ldb_), 0,  tid); \
    g3_issue(smb + STG, Ah, Al, Bh, Bl, bm, bn, (N_), (lda_), (ldb_), 32, tid); \
    const int l15 = lane & 15; \
    const int l7  = lane & 7; \
    const uint32_t aSel = (uint32_t)(lane >> 4); \
    const uint32_t bSel = (uint32_t)(l15 >> 3); \
    const uint32_t swzA = (uint32_t)((l15 >> 1) & 3); \
    const uint32_t swzB = (uint32_t)((l7 >> 1) & 3); \
    const uint32_t aBase = smb + (uint32_t)((wm * 64 + l15) * 64); \
    const uint32_t bBase = smb + 2u * MOFF + (uint32_t)((wn * 32 + l7) * 64); \
    for (int c = 0; c < nc; c++) { \
        asm volatile("cp.async.wait_group 1;" ::: "memory"); \
        __syncthreads(); \
        if (c + 2 < nc) { \
            g3_issue(smb + (uint32_t)((c + 2) % 3) * STG, \
                     Ah, Al, Bh, Bl, bm, bn, (N_), (lda_), (ldb_), (c + 2) << 5, tid); \
        } else { \
            asm volatile("cp.async.commit_group;" ::: "memory"); \
        } \
        const uint32_t so = (uint32_t)(c % 3) * STG; \
        _Pragma("unroll") \
        for (int kk = 0; kk < 2; kk++) { \
            const uint32_t cA = (uint32_t)(kk * 2) + aSel; \
            const uint32_t cB = (uint32_t)(kk * 2) + bSel; \
            unsigned bhf[4][2], blf[4][2]; \
            _Pragma("unroll") \
            for (int nf = 0; nf < 4; nf++) { \
                uint32_t ad = bBase + so + (uint32_t)(nf * 512) + ((cB ^ swzB) << 4); \
                LDMX2(bhf[nf], ad); \
                LDMX2(blf[nf], ad + MOFF); \
            } \
            _Pragma("unroll") \
            for (int mf = 0; mf < 4; mf++) { \
                uint32_t ad = aBase + so + (uint32_t)(mf * 1024) + ((cA ^ swzA) << 4); \
                unsigned ahf[4], alf[4]; \
                LDMX4(ahf, ad); \
                LDMX4(alf, ad + MOFF); \
                _Pragma("unroll") \
                for (int nf = 0; nf < 4; nf++) { \
                    MMA16816(acc[mf][nf], ahf, bhf[nf]); \
                    MMA16816(acc[mf][nf], ahf, blf[nf]); \
                    MMA16816(acc[mf][nf], alf, bhf[nf]); \
                } \
            } \
        } \
    }

__global__ __launch_bounds__(256, 2) void gemm3(
    const __nv_bfloat16* __restrict__ Ah, const __nv_bfloat16* __restrict__ Al,
    const __nv_bfloat16* __restrict__ Bh, const __nv_bfloat16* __restrict__ Bl,
    float* __restrict__ C,
    int M, int N, int K, int lda, int ldb, int ldc)
{
    extern __shared__ char sm[];
    const int tid  = threadIdx.x;
    const int lane = tid & 31;
    const int wid  = tid >> 5;
    const int g    = lane >> 2;
    const int tig  = lane & 3;
    const int wm   = wid >> 2;
    const int wn   = wid & 3;
    const int bm = blockIdx.y * 128;
    const int bn = blockIdx.x * 128;
    const uint32_t smb = smem_u32(sm);

    float acc[4][4][4];
#pragma unroll
    for (int i = 0; i < 4; i++)
#pragma unroll
        for (int j = 0; j < 4; j++)
#pragma unroll
            for (int q = 0; q < 4; q++) acc[i][j][q] = 0.f;

    G3_MAINLOOP(K, lda, ldb, N)

#pragma unroll
    for (int mf = 0; mf < 4; mf++) {
#pragma unroll
        for (int nf = 0; nf < 4; nf++) {
            int row = bm + wm * 64 + mf * 16 + g;
            int col = bn + wn * 32 + nf * 8 + 2 * tig;
            if (col < N) {
                float* p0 = C + (long long)row * ldc + col;
                p0[0] = acc[mf][nf][0];
                p0[1] = acc[mf][nf][1];
                float* p1 = p0 + (long long)8 * ldc;
                p1[0] = acc[mf][nf][2];
                p1[1] = acc[mf][nf][3];
            }
        }
    }
}

// ==== kv_proj GEMM with fused epilogue: K-nope -> Kh/Kl, V -> Vt (transposed) =
// n-tile 2t   = head t, k_nope d 0..127  -> Kh/Kl [bh][s][0..128)
// n-tile 2t+1 = head t, v d 0..127       -> Vth/Vtl [bh][d][s] via smem transpose
__global__ __launch_bounds__(256, 2) void gemm_kv(
    const __nv_bfloat16* __restrict__ Ah, const __nv_bfloat16* __restrict__ Al,
    const __nv_bfloat16* __restrict__ Bh, const __nv_bfloat16* __restrict__ Bl,
    __nv_bfloat16* __restrict__ Kh, __nv_bfloat16* __restrict__ Kl,
    __nv_bfloat16* __restrict__ Vth, __nv_bfloat16* __restrict__ Vtl)
{
    extern __shared__ char sm[];
    const int tid  = threadIdx.x;
    const int lane = tid & 31;
    const int wid  = tid >> 5;
    const int g    = lane >> 2;
    const int tig  = lane & 3;
    const int wm   = wid >> 2;
    const int wn   = wid & 3;
    const int bm = blockIdx.y * 128;
    const int bn = blockIdx.x * 128;
    const int h   = blockIdx.x >> 1;
    const int isV = blockIdx.x & 1;
    const uint32_t smb = smem_u32(sm);

    float acc[4][4][4];
#pragma unroll
    for (int i = 0; i < 4; i++)
#pragma unroll
        for (int j = 0; j < 4; j++)
#pragma unroll
            for (int q = 0; q < 4; q++) acc[i][j][q] = 0.f;

    G3_MAINLOOP(KV_RANK, KV_RANK, KV_RANK, KV_PROJ)

    const int b = bm >> 11;               // token block -> batch
    const int sbase = bm & 2047;

    if (!isV) {
        // K-nope: write [bh][s][d] (16B segments)
#pragma unroll
        for (int mf = 0; mf < 4; mf++) {
#pragma unroll
            for (int nf = 0; nf < 4; nf++) {
                int s = sbase + wm * 64 + mf * 16 + g;
                int d = wn * 32 + nf * 8 + 2 * tig;
                long long o0 = ((long long)(b * HH + h) * SS + s) * QKD + d;
                long long o1 = o0 + 8ll * QKD;
                unsigned hh, ll;
                packP(acc[mf][nf][0], acc[mf][nf][1], hh, ll);
                *(unsigned*)(Kh + o0) = hh;
                *(unsigned*)(Kl + o0) = ll;
                packP(acc[mf][nf][2], acc[mf][nf][3], hh, ll);
                *(unsigned*)(Kh + o1) = hh;
                *(unsigned*)(Kl + o1) = ll;
            }
        }
    } else {
        // V: stage fp32 tile in smem, then lanes sweep s (coalesced 128B/warp)
        __syncthreads();
        float* vs = (float*)sm;           // [128 d][132 pitch]
#pragma unroll
        for (int mf = 0; mf < 4; mf++) {
#pragma unroll
            for (int nf = 0; nf < 4; nf++) {
                int rl = wm * 64 + mf * 16 + g;        // s local
                int cl = wn * 32 + nf * 8 + 2 * tig;   // d local
                vs[cl * 132 + rl]           = acc[mf][nf][0];
                vs[(cl + 1) * 132 + rl]     = acc[mf][nf][1];
                vs[cl * 132 + rl + 8]       = acc[mf][nf][2];
                vs[(cl + 1) * 132 + rl + 8] = acc[mf][nf][3];
            }
        }
        __syncthreads();
        const long long vbase = (long long)((b * HH + h) * VDIM) * SS + sbase;
#pragma unroll
        for (int it = 0; it < 32; it++) {
            int idx = tid + it * 256;      // 0..8191 = 128 d x 64 s-pairs
            int d   = idx >> 6;
            int sp  = idx & 63;            // s-pair
            const float* src = vs + d * 132 + sp * 2;
            unsigned hh, ll;
            packP(src[0], src[1], hh, ll);
            long long o = vbase + (long long)d * SS + sp * 2;
            *(unsigned*)(Vth + o) = hh;
            *(unsigned*)(Vtl + o) = ll;
        }
    }
}

// ================= fused flash attention (bf16x3, online softmax) =============
#define FA_KOFF 98304u
#define FA_QLO  49152u
#define FA_VOFF 147456u
#define FA_SMEM 212992

__device__ __forceinline__ void fa_issueK(
    uint32_t smb, int stage,
    const __nv_bfloat16* __restrict__ Khp, const __nv_bfloat16* __restrict__ Klp,
    int c, int tid)
{
#pragma unroll
    for (int it = 0; it < 2; it++) {
        int u = tid + (it << 8);
        int r = u >> 2, sg = u & 3;
        int p = sg ^ ((r >> 1) & 3);
        uint32_t d = smb + FA_KOFF + (uint32_t)(stage * 16384 + r * 64 + p * 16);
        long long off = (long long)r * QKD + c * 32 + sg * 8;
        cp16(d,         Khp + off);
        cp16(d + 8192u, Klp + off);
    }
    asm volatile("cp.async.commit_group;" ::: "memory");
}

__device__ __forceinline__ void fa_issueV(
    uint32_t smb,
    const __nv_bfloat16* __restrict__ Vhp, const __nv_bfloat16* __restrict__ Vlp,
    int j, int tid)
{
#pragma unroll
    for (int it = 0; it < 8; it++) {
        int u = tid + (it << 8);
        int cb = u >> 9, v = u & 511;
        int r = v >> 2, sg = v & 3;
        int p = sg ^ ((r >> 1) & 3);
        uint32_t d = smb + FA_VOFF + (uint32_t)(cb * 16384 + r * 64 + p * 16);
        long long off = (long long)r * SS + j * 128 + cb * 32 + sg * 8;
        cp16(d,         Vhp + off);
        cp16(d + 8192u, Vlp + off);
    }
    asm volatile("cp.async.commit_group;" ::: "memory");
}

__global__ __launch_bounds__(256, 1) void fa_kernel(
    const __nv_bfloat16* __restrict__ Qh, const __nv_bfloat16* __restrict__ Ql,
    const __nv_bfloat16* __restrict__ Kh, const __nv_bfloat16* __restrict__ Kl,
    const __nv_bfloat16* __restrict__ Vth, const __nv_bfloat16* __restrict__ Vtl,
    __nv_bfloat16* __restrict__ a2h, __nv_bfloat16* __restrict__ a2l)
{
    extern __shared__ char sm[];
    const int tid  = threadIdx.x;
    const int lane = tid & 31;
    const int wid  = tid >> 5;
    const int g    = lane >> 2;
    const int tig  = lane & 3;
    const int qt   = blockIdx.x;
    const int bh   = blockIdx.y;
    const int b    = bh >> 4, h = bh & 15;
    const uint32_t smb = smem_u32(sm);

    const long long qkBase = (long long)bh * SS * QKD;
    const __nv_bfloat16* QhB = Qh + qkBase + (long long)qt * 128 * QKD;
    const __nv_bfloat16* QlB = Ql + qkBase + (long long)qt * 128 * QKD;
    const __nv_bfloat16* KhB = Kh + qkBase;
    const __nv_bfloat16* KlB = Kl + qkBase;
    const __nv_bfloat16* VhB = Vth + (long long)bh * VDIM * SS;
    const __nv_bfloat16* VlB = Vtl + (long long)bh * VDIM * SS;

    {
#pragma unroll
        for (int c = 0; c < 6; c++) {
#pragma unroll
            for (int it = 0; it < 2; it++) {
                int u = tid + (it << 8);
                int r = u >> 2, sg = u & 3;
                int p = sg ^ ((r >> 1) & 3);
                uint32_t d = smb + (uint32_t)(c * 8192 + r * 64 + p * 16);
                long long off = (long long)r * QKD + c * 32 + sg * 8;
                cp16(d,          QhB + off);
                cp16(d + FA_QLO, QlB + off);
            }
        }
        asm volatile("cp.async.commit_group;" ::: "memory");
    }
    fa_issueK(smb, 0, KhB, KlB, 0, tid);
    fa_issueK(smb, 1, KhB, KlB, 1, tid);

    float sacc[16][4], oacc[16][4];
    float m0 = -1e30f, m1 = -1e30f, l0 = 0.f, l1 = 0.f;
#pragma unroll
    for (int nf = 0; nf < 16; nf++)
#pragma unroll
        for (int q = 0; q < 4; q++) oacc[nf][q] = 0.f;

    const int l15 = lane & 15;
    const int l7  = lane & 7;
    const uint32_t aSel = (uint32_t)(lane >> 4);
    const uint32_t bSel = (uint32_t)(l15 >> 3);
    const uint32_t swzA = (uint32_t)((l15 >> 1) & 3);
    const uint32_t swzB = (uint32_t)((l7 >> 1) & 3);
    const uint32_t aRow = smb + (uint32_t)((wid * 16 + l15) * 64);
    const uint32_t kRow = smb + FA_KOFF + (uint32_t)(l7 * 64);
    const uint32_t vRow = smb + FA_VOFF + (uint32_t)(l7 * 64);

    for (int j = 0; j < 16; j++) {
        __syncthreads();
        fa_issueV(smb, VhB, VlB, j, tid);

#pragma unroll
        for (int nf = 0; nf < 16; nf++) {
            sacc[nf][0] = 0.f; sacc[nf][1] = 0.f; sacc[nf][2] = 0.f; sacc[nf][3] = 0.f;
        }

        for (int c = 0; c < 6; c++) {
            const int gc = j * 6 + c;
            if (c < 2) asm volatile("cp.async.wait_group 2;" ::: "memory");
            else       asm volatile("cp.async.wait_group 1;" ::: "memory");
            __syncthreads();

            const int gcI = gc + 2;
            if (gcI < 96) {
                const int jI = gcI / 6, cI = gcI % 6;
                fa_issueK(smb, gcI % 3,
                          KhB + (long long)jI * 128 * QKD,
                          KlB + (long long)jI * 128 * QKD, cI, tid);
            } else {
                asm volatile("cp.async.commit_group;" ::: "memory");
            }

            const uint32_t aB = aRow + (uint32_t)(c * 8192);
            const uint32_t kB = kRow + (uint32_t)((gc % 3) * 16384);
#pragma unroll
            for (int kk = 0; kk < 2; kk++) {
                const uint32_t cA = (uint32_t)(kk * 2) + aSel;
                const uint32_t cB = (uint32_t)(kk * 2) + bSel;
                uint32_t aAd = aB + ((cA ^ swzA) << 4);
                unsigned ah[4], al[4];
                LDMX4(ah, aAd);
                LDMX4(al, aAd + FA_QLO);
#pragma unroll
                for (int nf = 0; nf < 16; nf++) {
                    uint32_t bAd = kB + (uint32_t)(nf * 512) + ((cB ^ swzB) << 4);
                    unsigned kh2[2], kl2[2];
                    LDMX2(kh2, bAd);
                    LDMX2(kl2, bAd + 8192u);
                    MMA16816(sacc[nf], ah, kh2);
                    MMA16816(sacc[nf], ah, kl2);
                    MMA16816(sacc[nf], al, kh2);
                }
            }
        }

        float mx0 = -1e30f, mx1 = -1e30f;
#pragma unroll
        for (int nf = 0; nf < 16; nf++) {
            mx0 = fmaxf(mx0, fmaxf(sacc[nf][0], sacc[nf][1]));
            mx1 = fmaxf(mx1, fmaxf(sacc[nf][2], sacc[nf][3]));
        }
        mx0 = fmaxf(mx0, __shfl_xor_sync(0xffffffffu, mx0, 1));
        mx0 = fmaxf(mx0, __shfl_xor_sync(0xffffffffu, mx0, 2));
        mx1 = fmaxf(mx1, __shfl_xor_sync(0xffffffffu, mx1, 1));
        mx1 = fmaxf(mx1, __shfl_xor_sync(0xffffffffu, mx1, 2));
        const float mn0 = fmaxf(m0, mx0 * ATT_SCALE);
        const float mn1 = fmaxf(m1, mx1 * ATT_SCALE);
        const float cf0 = __expf(m0 - mn0);
        const float cf1 = __expf(m1 - mn1);
        float s0 = 0.f, s1 = 0.f;
#pragma unroll
        for (int nf = 0; nf < 16; nf++) {
            float p0 = __expf(sacc[nf][0] * ATT_SCALE - mn0);
            float p1 = __expf(sacc[nf][1] * ATT_SCALE - mn0);
            float p2 = __expf(sacc[nf][2] * ATT_SCALE - mn1);
            float p3 = __expf(sacc[nf][3] * ATT_SCALE - mn1);
            sacc[nf][0] = p0; sacc[nf][1] = p1; sacc[nf][2] = p2; sacc[nf][3] = p3;
            s0 += p0 + p1; s1 += p2 + p3;
        }
        s0 += __shfl_xor_sync(0xffffffffu, s0, 1);
        s0 += __shfl_xor_sync(0xffffffffu, s0, 2);
        s1 += __shfl_xor_sync(0xffffffffu, s1, 1);
        s1 += __shfl_xor_sync(0xffffffffu, s1, 2);
        l0 = l0 * cf0 + s0; l1 = l1 * cf1 + s1;
        m0 = mn0; m1 = mn1;
#pragma unroll
        for (int nf = 0; nf < 16; nf++) {
            oacc[nf][0] *= cf0; oacc[nf][1] *= cf0;
            oacc[nf][2] *= cf1; oacc[nf][3] *= cf1;
        }

#pragma unroll
        for (int kc = 0; kc < 8; kc++) {
            unsigned ah[4], al[4];
            packP(sacc[2 * kc][0],     sacc[2 * kc][1],     ah[0], al[0]);
            packP(sacc[2 * kc][2],     sacc[2 * kc][3],     ah[1], al[1]);
            packP(sacc[2 * kc + 1][0], sacc[2 * kc + 1][1], ah[2], al[2]);
            packP(sacc[2 * kc + 1][2], sacc[2 * kc + 1][3], ah[3], al[3]);
            const uint32_t vB = vRow + (uint32_t)((kc >> 1) * 16384);
            const uint32_t cV = (uint32_t)((kc & 1) * 2) + bSel;
#pragma unroll
            for (int nf = 0; nf < 16; nf++) {
                uint32_t bAd = vB + (uint32_t)(nf * 512) + ((cV ^ swzB) << 4);
                unsigned vh2[2], vl2[2];
                LDMX2(vh2, bAd);
                LDMX2(vl2, bAd + 8192u);
                MMA16816(oacc[nf], ah, vh2);
                MMA16816(oacc[nf], ah, vl2);
                MMA16816(oacc[nf], al, vh2);
            }
        }
    }

    const float li0 = 1.f / l0, li1 = 1.f / l1;
    const int srow = qt * 128 + wid * 16 + g;
    const long long base0 = ((long long)(b * SS) + srow) * (HH * VDIM) + h * VDIM;
    const long long base1 = base0 + 8ll * (HH * VDIM);
#pragma unroll
    for (int nf = 0; nf < 16; nf++) {
        const int d = nf * 8 + 2 * tig;
        unsigned hh, ll;
        packP(oacc[nf][0] * li0, oacc[nf][1] * li0, hh, ll);
        *(unsigned*)(a2h + base0 + d) = hh;
        *(unsigned*)(a2l + base0 + d) = ll;
        packP(oacc[nf][2] * li1, oacc[nf][3] * li1, hh, ll);
        *(unsigned*)(a2h + base1 + d) = hh;
        *(unsigned*)(a2l + base1 + d) = ll;
    }
}

// ---------------- fp32 -> bf16 hi/lo converter ----------------
__global__ void convert_kernel(const float* __restrict__ in,
                               __nv_bfloat16* __restrict__ hp,
                               __nv_bfloat16* __restrict__ lp, long long n4)
{
    for (long long i = (long long)blockIdx.x * 256 + threadIdx.x; i < n4;
         i += (long long)gridDim.x * 256) {
        float4 v = ((const float4*)in)[i];
        __nv_bfloat16 h0, h1, h2, h3, l0, l1, l2, l3;
        split2(v.x, h0, l0); split2(v.y, h1, l1);
        split2(v.z, h2, l2); split2(v.w, h3, l3);
        uint2 hh, ll;
        hh.x = ((unsigned)__bfloat16_as_ushort(h1) << 16) | __bfloat16_as_ushort(h0);
        hh.y = ((unsigned)__bfloat16_as_ushort(h3) << 16) | __bfloat16_as_ushort(h2);
        ll.x = ((unsigned)__bfloat16_as_ushort(l1) << 16) | __bfloat16_as_ushort(l0);
        ll.y = ((unsigned)__bfloat16_as_ushort(l3) << 16) | __bfloat16_as_ushort(l2);
        ((uint2*)hp)[i] = hh;
        ((uint2*)lp)[i] = ll;
    }
}

// ---------------- rmsnorm over KV_RANK (reads merged qkv buffer) --------------
__global__ void rmsnorm_kernel(const float* __restrict__ qkv,
                               const float* __restrict__ w,
                               __nv_bfloat16* __restrict__ oh,
                               __nv_bfloat16* __restrict__ ol)
{
    const int row = blockIdx.x;
    const float* x = qkv + (long long)row * QKV_N + HH * QKD;
    __shared__ float red[256];
    float ss = 0.f;
    for (int i = threadIdx.x; i < KV_RANK; i += 256) { float v = x[i]; ss += v * v; }
    red[threadIdx.x] = ss; __syncthreads();
    for (int st = 128; st > 0; st >>= 1) {
        if (threadIdx.x < st) red[threadIdx.x] += red[threadIdx.x + st];
        __syncthreads();
    }
    float scale = rsqrtf(red[0] / (float)KV_RANK + EPSV);
    for (int i = threadIdx.x; i < KV_RANK; i += 256) {
        float v = x[i] * scale * w[i];
        __nv_bfloat16 h, l; split2(v, h, l);
        oh[(long long)row * KV_RANK + i] = h;
        ol[(long long)row * KV_RANK + i] = l;
    }
}

// ---------------- RoPE prep: Q (full) + K rope-part only ----------------------
__global__ void prepare_kernel(const float* __restrict__ qkv,
                               const float* __restrict__ cosb,
                               const float* __restrict__ sinb,
                               __nv_bfloat16* __restrict__ Qh, __nv_bfloat16* __restrict__ Ql,
                               __nv_bfloat16* __restrict__ Kh, __nv_bfloat16* __restrict__ Kl)
{
    const int bs = blockIdx.x;
    const int b = bs / SS, s = bs % SS;
    const float* cs = cosb + (long long)s * ROPE;
    const float* sn = sinb + (long long)s * ROPE;

    __shared__ float kpe[ROPE];
    if (threadIdx.x < ROPE) {
        int j = threadIdx.x;
        const float* kp = qkv + (long long)bs * QKV_N + HH * QKD + KV_RANK;
        float x  = kp[j];
        float xr = (j < 32) ? -kp[j + 32] : kp[j - 32];
        kpe[j] = x * cs[j] + xr * sn[j];
    }
    __syncthreads();

    const float* qrow = qkv + (long long)bs * QKV_N;

    for (int idx = threadIdx.x; idx < HH * QKD; idx += blockDim.x) {
        int h = idx / QKD, d = idx % QKD;
        long long off = (((long long)(b * HH + h)) * SS + s) * QKD + d;
        float qv;
        if (d < NOPE) {
            qv = qrow[h * QKD + d];
        } else {
            int j = d - NOPE;
            float x  = qrow[h * QKD + NOPE + j];
            float xr = (j < 32) ? -qrow[h * QKD + NOPE + j + 32]
                                :  qrow[h * QKD + NOPE + j - 32];
            qv = x * cs[j] + xr * sn[j];
        }
        __nv_bfloat16 hh, ll;
        split2(qv, hh, ll); Qh[off] = hh; Ql[off] = ll;
    }
    // K rope part (d 128..191), broadcast across heads
    for (int idx = threadIdx.x; idx < HH * ROPE; idx += blockDim.x) {
        int h = idx >> 6, j = idx & 63;
        long long off = (((long long)(b * HH + h)) * SS + s) * QKD + NOPE + j;
        __nv_bfloat16 hh, ll; split2(kpe[j], hh, ll);
        Kh[off] = hh; Kl[off] = ll;
    }
}

// ---------------- launch ----------------
extern "C" void kernel_launch(void* const* d_in, const int* in_sizes, int n_in,
                              void* d_out, int out_size)
{
    const float* x    = (const float*)d_in[0];
    const float* cosb = (const float*)d_in[1];
    const float* sinb = (const float*)d_in[2];
    const float* wq   = (const float*)d_in[3];
    const float* wkva = (const float*)d_in[4];
    const float* kvw  = (const float*)d_in[5];
    const float* wkvb = (const float*)d_in[6];
    const float* wo   = (const float*)d_in[7];
    float* out = (float*)d_out;

    cudaFuncSetAttribute(gemm3,   cudaFuncAttributeMaxDynamicSharedMemorySize, GEMM3_SMEM);
    cudaFuncSetAttribute(gemm_kv, cudaFuncAttributeMaxDynamicSharedMemorySize, GEMM3_SMEM);
    cudaFuncSetAttribute(fa_kernel, cudaFuncAttributeMaxDynamicSharedMemorySize, FA_SMEM);

    float *qkv;
    cudaGetSymbolAddress((void**)&qkv, g_qkv);

    __nv_bfloat16 *xh, *xl, *wqkvh, *wqkvl, *wkvbh, *wkvbl, *woh, *wol;
    __nv_bfloat16 *kvnh, *kvnl, *Qh, *Ql, *Kh, *Kl, *Vth, *Vtl, *a2h, *a2l;
    cudaGetSymbolAddress((void**)&xh,    g_xh);    cudaGetSymbolAddress((void**)&xl,    g_xl);
    cudaGetSymbolAddress((void**)&wqkvh, g_wqkvh); cudaGetSymbolAddress((void**)&wqkvl, g_wqkvl);
    cudaGetSymbolAddress((void**)&wkvbh, g_wkvbh); cudaGetSymbolAddress((void**)&wkvbl, g_wkvbl);
    cudaGetSymbolAddress((void**)&woh,   g_woh);   cudaGetSymbolAddress((void**)&wol,   g_wol);
    cudaGetSymbolAddress((void**)&kvnh,  g_kvnh);  cudaGetSymbolAddress((void**)&kvnl,  g_kvnl);
    cudaGetSymbolAddress((void**)&Qh,    g_Qh);    cudaGetSymbolAddress((void**)&Ql,    g_Ql);
    cudaGetSymbolAddress((void**)&Kh,    g_Kh);    cudaGetSymbolAddress((void**)&Kl,    g_Kl);
    cudaGetSymbolAddress((void**)&Vth,   g_Vth);   cudaGetSymbolAddress((void**)&Vtl,   g_Vtl);
    cudaGetSymbolAddress((void**)&a2h,   g_a2h);   cudaGetSymbolAddress((void**)&a2l,   g_a2l);

    const int M = BB * SS;   // 4096

    // 0) pre-split inputs/weights to bf16 hi/lo (wq+wkv_a share one buffer)
    convert_kernel<<<1024, 256>>>(x,    xh,    xl,    (long long)BB * SS * DD / 4);
    convert_kernel<<<1024, 256>>>(wq,   wqkvh, wqkvl, (long long)(HH * QKD) * DD / 4);
    convert_kernel<<<1024, 256>>>(wkva, wqkvh + (size_t)(HH * QKD) * DD,
                                        wqkvl + (size_t)(HH * QKD) * DD,
                                        (long long)KV_A * DD / 4);
    convert_kernel<<<1024, 256>>>(wkvb, wkvbh, wkvbl, (long long)KV_PROJ * KV_RANK / 4);
    convert_kernel<<<1024, 256>>>(wo,   woh,   wol,   (long long)DD * DD / 4);

    // 1) qkv_raw = X @ [wq; wkv_a]^T   [4096,3648] K=2048
    gemm3<<<dim3((QKV_N + 127) / 128, M / 128, 1), 256, GEMM3_SMEM>>>(
        xh, xl, wqkvh, wqkvl, qkv, M, QKV_N, DD, DD, DD, QKV_N);

    // 2) rmsnorm -> bf16 hi/lo
    rmsnorm_kernel<<<M, 256>>>(qkv, kvw, kvnh, kvnl);

    // 3) kv_proj GEMM with fused K/V epilogue (writes Kh/Kl d<128 and Vt)
    gemm_kv<<<dim3(KV_PROJ / 128, M / 128, 1), 256, GEMM3_SMEM>>>(
        kvnh, kvnl, wkvbh, wkvbl, Kh, Kl, Vth, Vtl);

    // 4) RoPE prep: Q full + K rope-part
    prepare_kernel<<<M, 256>>>(qkv, cosb, sinb, Qh, Ql, Kh, Kl);

    // 5) fused attention -> a2h/a2l
    fa_kernel<<<dim3(SS / 128, BB * HH, 1), 256, FA_SMEM>>>(
        Qh, Ql, Kh, Kl, Vth, Vtl, a2h, a2l);

    // 6) out = attn2 @ wo^T      [4096,2048] K=2048
    gemm3<<<dim3(DD / 128, M / 128, 1), 256, GEMM3_SMEM>>>(
        a2h, a2l, woh, wol, out, M, DD, HH * VDIM, HH * VDIM, HH * VDIM, DD);
}